// round 15
// baseline (speedup 1.0000x reference)
#include <cuda_runtime.h>
#include <cuda_bf16.h>
#include <cuda_fp8.h>
#include <stdint.h>

#define TOKENS 65536   // B*N = 16*4096
#define FD     256
#define MSZ    4096
#define TOPK   8
#define NCAND  16      // fp8-ranked candidates per row, rescored exactly

// ---------------- device scratch (referenced ONLY from device code) ----------------
__device__ float          g_q   [TOKENS * FD];   // projected q, fp32 (exact rescore)
__device__ uint8_t        g_q8  [TOKENS * FD];   // projected q, e4m3 (fp8 ranking)
__device__ uint8_t        g_k8  [MSZ * FD];      // memory_keys e4m3
__device__ int            g_idx [TOKENS * NCAND];// top-16 candidate indices per row
__device__ __nv_bfloat16  g_xhi [TOKENS * FD];   // raw query hi
__device__ __nv_bfloat16  g_xlo [TOKENS * FD];   // raw query lo
__device__ __nv_bfloat16  g_rhi [TOKENS * FD];   // retrieved hi
__device__ __nv_bfloat16  g_rlo [TOKENS * FD];   // retrieved lo
__device__ __nv_bfloat16  g_hhi [TOKENS * FD];   // hidden (relu) hi
__device__ __nv_bfloat16  g_hlo [TOKENS * FD];   // hidden (relu) lo
__device__ __nv_bfloat16  g_WqThi[FD * FD],     g_WqTlo[FD * FD];       // [n][k]
__device__ __nv_bfloat16  g_W1Thi[FD * 2 * FD], g_W1Tlo[FD * 2 * FD];   // [n][k], k=512
__device__ __nv_bfloat16  g_W2Thi[FD * FD],     g_W2Tlo[FD * FD];       // [n][k]

// ---------------- cp.async / ldmatrix helpers ----------------
__device__ __forceinline__ void cp16(void* sdst, const void* gsrc) {
    uint32_t s = (uint32_t)__cvta_generic_to_shared(sdst);
    asm volatile("cp.async.cg.shared.global [%0], [%1], 16;\n" :: "r"(s), "l"(gsrc));
}
__device__ __forceinline__ void cp_commit() {
    asm volatile("cp.async.commit_group;\n" ::: "memory");
}
__device__ __forceinline__ void cp_wait1() {
    asm volatile("cp.async.wait_group 1;\n" ::: "memory");
}
__device__ __forceinline__ void ldsm4(uint32_t* r, const void* p) {
    uint32_t a = (uint32_t)__cvta_generic_to_shared(p);
    asm volatile("ldmatrix.sync.aligned.m8n8.x4.shared.b16 {%0,%1,%2,%3}, [%4];"
                 : "=r"(r[0]), "=r"(r[1]), "=r"(r[2]), "=r"(r[3]) : "r"(a));
}
// pack 2 floats -> e4m3x2 (low byte = first arg)
__device__ __forceinline__ uint16_t f2_to_e4m3x2(float lo, float hi) {
    uint16_t d;
    asm("cvt.rn.satfinite.e4m3x2.f32 %0, %1, %2;" : "=h"(d) : "f"(hi), "f"(lo));
    return d;
}

// ---------------- conversions ----------------
__global__ __launch_bounds__(256)
void cvt_kw_kernel(const float* __restrict__ mk, const float* __restrict__ Wq,
                   const float* __restrict__ W1, const float* __restrict__ W2) {
    int i = blockIdx.x * blockDim.x + threadIdx.x;
    const int KP = MSZ * FD / 2;
    if (i < KP) {
        uint16_t p = f2_to_e4m3x2(mk[2 * i], mk[2 * i + 1]);
        *(uint16_t*)&g_k8[2 * i] = p;
        return;
    }
    int j = i - KP;
    const float* W; __nv_bfloat16 *hiT, *loT; int K;
    if (j < FD * FD)          { W = Wq; hiT = g_WqThi; loT = g_WqTlo; K = FD; }
    else if (j < 3 * FD * FD) { j -= FD * FD; W = W1; hiT = g_W1Thi; loT = g_W1Tlo; K = 2 * FD; }
    else if (j < 4 * FD * FD) { j -= 3 * FD * FD; W = W2; hiT = g_W2Thi; loT = g_W2Tlo; K = FD; }
    else return;
    int n = j / K, k = j - n * K;
    float x = W[(size_t)k * FD + n];
    __nv_bfloat16 h = __float2bfloat16(x);
    hiT[j] = h;
    loT[j] = __float2bfloat16(x - __bfloat162float(h));
}

__global__ __launch_bounds__(256)
void cvt_query_split_kernel(const float* __restrict__ src) {
    int i = blockIdx.x * blockDim.x + threadIdx.x;
    if (i < TOKENS * FD) {
        float x = src[i];
        __nv_bfloat16 h = __float2bfloat16(x);
        g_xhi[i] = h;
        g_xlo[i] = __float2bfloat16(x - __bfloat162float(h));
    }
}

// ---------------- mma helpers ----------------
__device__ __forceinline__ void mma16816(float* d, uint32_t a0, uint32_t a1,
                                         uint32_t a2, uint32_t a3,
                                         uint32_t b0, uint32_t b1) {
    asm volatile(
        "mma.sync.aligned.m16n8k16.row.col.f32.bf16.bf16.f32 "
        "{%0,%1,%2,%3}, {%4,%5,%6,%7}, {%8,%9}, {%0,%1,%2,%3};\n"
        : "+f"(d[0]), "+f"(d[1]), "+f"(d[2]), "+f"(d[3])
        : "r"(a0), "r"(a1), "r"(a2), "r"(a3), "r"(b0), "r"(b1));
}
__device__ __forceinline__ void mma16832f8(float* d, uint32_t a0, uint32_t a1,
                                           uint32_t a2, uint32_t a3,
                                           uint32_t b0, uint32_t b1) {
    asm volatile(
        "mma.sync.aligned.m16n8k32.row.col.f32.e4m3.e4m3.f32 "
        "{%0,%1,%2,%3}, {%4,%5,%6,%7}, {%8,%9}, {%0,%1,%2,%3};\n"
        : "+f"(d[0]), "+f"(d[1]), "+f"(d[2]), "+f"(d[3])
        : "r"(a0), "r"(a1), "r"(a2), "r"(a3), "r"(b0), "r"(b1));
}

// ---------------- split-bf16 tensor-core GEMM, 2-stage cp.async, ldmatrix ----------------
#define BG_SMEM 81920

template<int MODE>
__device__ __forceinline__ void bgemm_load_chunk(__nv_bfloat16* As, __nv_bfloat16* Bs,
                                                 int st, int kt, int row0, int col0,
                                                 int tid, int Ktot) {
    const __nv_bfloat16 *ah, *al;
    int kof;
    if (MODE == 1 && kt >= 256) { ah = g_rhi; al = g_rlo; kof = kt - 256; }
    else if (MODE == 2)         { ah = g_hhi; al = g_hlo; kof = kt; }
    else                        { ah = g_xhi; al = g_xlo; kof = kt; }
    const __nv_bfloat16* bh = (MODE == 0) ? g_WqThi : (MODE == 1) ? g_W1Thi : g_W2Thi;
    const __nv_bfloat16* bl = (MODE == 0) ? g_WqTlo : (MODE == 1) ? g_W1Tlo : g_W2Tlo;
    const int lr = tid >> 1, lk = (tid & 1) * 16;
    const size_t aoff = (size_t)(row0 + lr) * FD + kof + lk;
    const size_t boff = (size_t)(col0 + lr) * Ktot + kt + lk;
    cp16(&As[((st * 2 + 0) * 128 + lr) * 40 + lk],     &ah[aoff]);
    cp16(&As[((st * 2 + 0) * 128 + lr) * 40 + lk + 8], &ah[aoff + 8]);
    cp16(&As[((st * 2 + 1) * 128 + lr) * 40 + lk],     &al[aoff]);
    cp16(&As[((st * 2 + 1) * 128 + lr) * 40 + lk + 8], &al[aoff + 8]);
    cp16(&Bs[((st * 2 + 0) * 128 + lr) * 40 + lk],     &bh[boff]);
    cp16(&Bs[((st * 2 + 0) * 128 + lr) * 40 + lk + 8], &bh[boff + 8]);
    cp16(&Bs[((st * 2 + 1) * 128 + lr) * 40 + lk],     &bl[boff]);
    cp16(&Bs[((st * 2 + 1) * 128 + lr) * 40 + lk + 8], &bl[boff + 8]);
}

template<int MODE>
__global__ __launch_bounds__(256, 2)
void bgemm(const float* __restrict__ bias, float* __restrict__ Cout) {
    extern __shared__ char dynsmem[];
    __nv_bfloat16* As = (__nv_bfloat16*)dynsmem;
    __nv_bfloat16* Bs = As + 2 * 2 * 128 * 40;

    const int tid  = threadIdx.x;
    const int lane = tid & 31;
    const int wid  = tid >> 5;
    const int wm = wid & 3, wn = wid >> 2;
    const int row0 = blockIdx.y * 128;
    const int col0 = blockIdx.x * 128;
    const int Ktot = (MODE == 1) ? 512 : 256;
    const int NC   = Ktot / 32;

    const int lrow = (lane & 7) + ((lane >> 3) & 1) * 8;
    const int lcol = (lane >> 4) * 8;
    const int brow = (lane & 7) + (lane >> 4) * 8;
    const int bcol = ((lane >> 3) & 1) * 8;

    float acc[2][8][4];
    #pragma unroll
    for (int mf = 0; mf < 2; mf++)
        #pragma unroll
        for (int nt = 0; nt < 8; nt++)
            #pragma unroll
            for (int i = 0; i < 4; i++) acc[mf][nt][i] = 0.f;

    bgemm_load_chunk<MODE>(As, Bs, 0, 0, row0, col0, tid, Ktot);
    cp_commit();

    for (int c = 0; c < NC; c++) {
        const int st = c & 1;
        if (c + 1 < NC)
            bgemm_load_chunk<MODE>(As, Bs, (c + 1) & 1, (c + 1) * 32, row0, col0, tid, Ktot);
        cp_commit();
        cp_wait1();
        __syncthreads();

        const int sH = (st * 2 + 0) * 128, sL = (st * 2 + 1) * 128;
        #pragma unroll
        for (int ks = 0; ks < 2; ks++) {
            const int k0 = ks * 16;
            uint32_t fah[2][4], fal[2][4];
            #pragma unroll
            for (int mf = 0; mf < 2; mf++) {
                const int r = wm * 32 + mf * 16 + lrow;
                ldsm4(fah[mf], &As[(sH + r) * 40 + k0 + lcol]);
                ldsm4(fal[mf], &As[(sL + r) * 40 + k0 + lcol]);
            }
            #pragma unroll
            for (int p = 0; p < 4; p++) {
                const int n0 = wn * 64 + p * 16 + brow;
                uint32_t fbh[4], fbl[4];
                ldsm4(fbh, &Bs[(sH + n0) * 40 + k0 + bcol]);
                ldsm4(fbl, &Bs[(sL + n0) * 40 + k0 + bcol]);
                #pragma unroll
                for (int half = 0; half < 2; half++) {
                    const int nt = 2 * p + half;
                    uint32_t bh0 = fbh[half * 2], bh1 = fbh[half * 2 + 1];
                    uint32_t bl0 = fbl[half * 2], bl1 = fbl[half * 2 + 1];
                    #pragma unroll
                    for (int mf = 0; mf < 2; mf++) {
                        mma16816(acc[mf][nt], fah[mf][0], fah[mf][1], fah[mf][2], fah[mf][3], bh0, bh1);
                        mma16816(acc[mf][nt], fah[mf][0], fah[mf][1], fah[mf][2], fah[mf][3], bl0, bl1);
                        mma16816(acc[mf][nt], fal[mf][0], fal[mf][1], fal[mf][2], fal[mf][3], bh0, bh1);
                    }
                }
            }
        }
        __syncthreads();
    }

    #pragma unroll
    for (int nt = 0; nt < 8; nt++) {
        const int col_g = col0 + wn * 64 + nt * 8 + (lane & 3) * 2;
        const float b0 = bias[col_g], b1 = bias[col_g + 1];
        #pragma unroll
        for (int mf = 0; mf < 2; mf++) {
            #pragma unroll
            for (int half = 0; half < 2; half++) {
                const int row_g = row0 + wm * 32 + mf * 16 + (lane >> 2) + half * 8;
                float v0 = acc[mf][nt][half * 2 + 0] + b0;
                float v1 = acc[mf][nt][half * 2 + 1] + b1;
                const size_t o = (size_t)row_g * FD + col_g;
                if (MODE == 0) {
                    g_q[o] = v0; g_q[o + 1] = v1;
                    *(uint16_t*)&g_q8[o] = f2_to_e4m3x2(v0, v1);
                } else if (MODE == 1) {
                    v0 = fmaxf(v0, 0.f); v1 = fmaxf(v1, 0.f);
                    __nv_bfloat162 ph, pl;
                    ph.x = __float2bfloat16(v0); ph.y = __float2bfloat16(v1);
                    pl.x = __float2bfloat16(v0 - __bfloat162float(ph.x));
                    pl.y = __float2bfloat16(v1 - __bfloat162float(ph.y));
                    *(__nv_bfloat162*)&g_hhi[o] = ph;
                    *(__nv_bfloat162*)&g_hlo[o] = pl;
                } else {
                    Cout[o] = v0; Cout[o + 1] = v1;
                }
            }
        }
    }
}

// ---------------- sim v6: fp8 m16n8k32 ranking, 64-row tile, 2 CTAs/SM ----------------
// block 256 thr (8 warps as 2m x 4n). Q tile 64x256B persistent; key tile 128 keys,
// k chunk 64B double-buffered (4 chunks/tile). simT [row][key]; scan 4 thr/row.
// smem: Aq 64*272 = 17408 | Bs 2*128*80 = 20480 | simT 64*132*4 = 33792 -> 71680
#define SIM_AQ_OFF   0
#define SIM_BS_OFF   17408
#define SIM_ST_OFF   37888
#define SIM_SMEM     71680

__global__ __launch_bounds__(256, 2)
void sim_topk_kernel() {
    extern __shared__ char dynsmem[];
    uint8_t* Aq   = (uint8_t*)(dynsmem + SIM_AQ_OFF);   // [r][272B]
    uint8_t* Bs   = (uint8_t*)(dynsmem + SIM_BS_OFF);   // [st][key][80B]
    float*   simT = (float*)(dynsmem + SIM_ST_OFF);     // [r][132]

    const int tid  = threadIdx.x;
    const int lane = tid & 31;
    const int wid  = tid >> 5;
    const int wm = wid & 1, wn = wid >> 1;      // 2m x 4n
    const int row0 = blockIdx.x * 64;
    const int srow = tid >> 2, qd = tid & 3;    // scan: 4 threads per row

    // ldmatrix lane address components (byte units for fp8)
    const int lrow  = (lane & 7) + ((lane >> 3) & 1) * 8;
    const int lcolB = (lane >> 4) * 16;
    const int brow  = (lane & 7) + (lane >> 4) * 8;
    const int bcolB = ((lane >> 3) & 1) * 16;

    float ts[8]; int ti[8];
    #pragma unroll
    for (int i = 0; i < 8; i++) { ts[i] = -3.4e38f; ti[i] = 0; }

    // persistent q tile: 64 rows x 256B (4 cp16/thread)
    {
        const int r = tid >> 2, s0 = tid & 3;
        #pragma unroll
        for (int j = 0; j < 4; j++) {
            const int seg = s0 + j * 4;
            cp16(&Aq[r * 272 + seg * 16], &g_q8[(size_t)(row0 + r) * FD + seg * 16]);
        }
    }
    // first key chunk (tile 0, sub 0, stage 0): 128 keys x 64B (2 cp16/thread)
    {
        const int r = tid >> 1, s0 = tid & 1;
        #pragma unroll
        for (int j = 0; j < 2; j++) {
            const int seg = s0 + j * 2;
            cp16(&Bs[(0 * 128 + r) * 80 + seg * 16], &g_k8[(size_t)r * FD + seg * 16]);
        }
    }
    cp_commit();

    float acc[2][4][4];

    const int NGC = (MSZ / 128) * 4;   // 128 chunks (4 per key tile, 64B k each)
    for (int gc = 0; gc < NGC; gc++) {
        const int st = gc & 1;
        if (gc + 1 < NGC) {
            const int mt2 = (gc + 1) >> 2, sub2 = (gc + 1) & 3;
            const int st2 = (gc + 1) & 1;
            const int r = tid >> 1, s0 = tid & 1;
            #pragma unroll
            for (int j = 0; j < 2; j++) {
                const int seg = s0 + j * 2;
                cp16(&Bs[(st2 * 128 + r) * 80 + seg * 16],
                     &g_k8[(size_t)(mt2 * 128 + r) * FD + sub2 * 64 + seg * 16]);
            }
        }
        cp_commit();
        cp_wait1();
        __syncthreads();

        if ((gc & 3) == 0) {
            #pragma unroll
            for (int mf = 0; mf < 2; mf++)
                #pragma unroll
                for (int nt = 0; nt < 4; nt++)
                    #pragma unroll
                    for (int i = 0; i < 4; i++) acc[mf][nt][i] = 0.f;
        }

        const int akb = (gc & 3) * 64;
        #pragma unroll
        for (int ks = 0; ks < 2; ks++) {           // 2 x 32B k-steps
            uint32_t a[2][4];
            #pragma unroll
            for (int mf = 0; mf < 2; mf++) {
                const int r = wm * 32 + mf * 16 + lrow;
                ldsm4(a[mf], &Aq[r * 272 + akb + ks * 32 + lcolB]);
            }
            #pragma unroll
            for (int t = 0; t < 2; t++) {
                const int n0 = wn * 32 + t * 16 + brow;
                uint32_t fb[4];
                ldsm4(fb, &Bs[(st * 128 + n0) * 80 + ks * 32 + bcolB]);
                #pragma unroll
                for (int half = 0; half < 2; half++) {
                    const int nt = 2 * t + half;
                    uint32_t b0 = fb[half * 2], b1 = fb[half * 2 + 1];
                    mma16832f8(acc[0][nt], a[0][0], a[0][1], a[0][2], a[0][3], b0, b1);
                    mma16832f8(acc[1][nt], a[1][0], a[1][1], a[1][2], a[1][3], b0, b1);
                }
            }
        }

        if ((gc & 3) == 3) {
            const int mt = gc >> 2;
            __syncthreads();
            // store sim tile [row][key]
            #pragma unroll
            for (int nt = 0; nt < 4; nt++) {
                const int key0 = wn * 32 + nt * 8 + (lane & 3) * 2;
                #pragma unroll
                for (int mf = 0; mf < 2; mf++) {
                    const int rw = wm * 32 + mf * 16 + (lane >> 2);
                    float2 p0 = make_float2(acc[mf][nt][0], acc[mf][nt][1]);
                    float2 p1 = make_float2(acc[mf][nt][2], acc[mf][nt][3]);
                    *(float2*)&simT[rw * 132 + key0]       = p0;
                    *(float2*)&simT[(rw + 8) * 132 + key0] = p1;
                }
            }
            __syncthreads();
            // scan: thread (srow, qd) covers keys { qd*4 + i*16 + j : i<8, j<4 }
            #pragma unroll
            for (int i = 0; i < 8; i++) {
                const int k0 = qd * 4 + i * 16;
                float4 v = *(const float4*)&simT[srow * 132 + k0];
                float m01 = fmaxf(v.x, v.y), m23 = fmaxf(v.z, v.w);
                if (fmaxf(m01, m23) > ts[7]) {
                    float vv[4] = {v.x, v.y, v.z, v.w};
                    #pragma unroll
                    for (int j = 0; j < 4; j++) {
                        if (vv[j] > ts[7]) {
                            ts[7] = vv[j]; ti[7] = mt * 128 + k0 + j;
                            #pragma unroll
                            for (int s = 7; s > 0; s--) {
                                if (ts[s] > ts[s - 1]) {
                                    float tf = ts[s]; ts[s] = ts[s - 1]; ts[s - 1] = tf;
                                    int   tt = ti[s]; ti[s] = ti[s - 1]; ti[s - 1] = tt;
                                }
                            }
                        }
                    }
                }
            }
            __syncthreads();
        } else {
            __syncthreads();
        }
    }

    // final merge: 4 partial top-8 lists per row -> top-16 candidates
    float* cand = simT;   // [tid][16]: 8 vals + 8 idx-bits
    #pragma unroll
    for (int i = 0; i < 8; i++) {
        cand[tid * 16 + i]     = ts[i];
        cand[tid * 16 + 8 + i] = __int_as_float(ti[i]);
    }
    __syncthreads();
    if (qd == 0) {
        float vs[NCAND]; int vi[NCAND];
        #pragma unroll
        for (int i = 0; i < 8; i++) { vs[i] = ts[i]; vi[i] = ti[i]; }
        #pragma unroll
        for (int i = 8; i < NCAND; i++) { vs[i] = -3.4e38f; vi[i] = 0; }
        #pragma unroll
        for (int other = 1; other < 4; other++) {
            const int ot = tid + other;
            #pragma unroll
            for (int i = 0; i < 8; i++) {
                float v = cand[ot * 16 + i];
                int  ix = __float_as_int(cand[ot * 16 + 8 + i]);
                if (v > vs[NCAND - 1]) {
                    vs[NCAND - 1] = v; vi[NCAND - 1] = ix;
                    #pragma unroll
                    for (int s = NCAND - 1; s > 0; s--) {
                        if (vs[s] > vs[s - 1]) {
                            float tf = vs[s]; vs[s] = vs[s - 1]; vs[s - 1] = tf;
                            int   tt = vi[s]; vi[s] = vi[s - 1]; vi[s - 1] = tt;
                        }
                    }
                }
            }
        }
        #pragma unroll
        for (int i = 0; i < NCAND; i++)
            g_idx[(size_t)(row0 + srow) * NCAND + i] = vi[i];
    }
}

// ---------------- exact fp32 rescore of 16 candidates + top-8 + softmax + gather ----------------
__global__ __launch_bounds__(256)
void retrieve_kernel(const float* __restrict__ keys, const float* __restrict__ vals) {
    const int gwarp = (int)((blockIdx.x * blockDim.x + threadIdx.x) >> 5);
    const int lane  = threadIdx.x & 31;
    if (gwarp >= TOKENS) return;

    const float* qrow = g_q + (size_t)gwarp * FD;
    float4 q1 = *(const float4*)&qrow[lane * 8];
    float4 q2 = *(const float4*)&qrow[lane * 8 + 4];

    int id[NCAND];
    #pragma unroll
    for (int i = 0; i < NCAND; i++) id[i] = g_idx[(size_t)gwarp * NCAND + i];

    float s[NCAND];
    #pragma unroll
    for (int i = 0; i < NCAND; i++) {
        const float* kr = keys + (size_t)id[i] * FD + lane * 8;
        float4 k1 = *(const float4*)&kr[0];
        float4 k2 = *(const float4*)&kr[4];
        float p = q1.x * k1.x + q1.y * k1.y + q1.z * k1.z + q1.w * k1.w
                + q2.x * k2.x + q2.y * k2.y + q2.z * k2.z + q2.w * k2.w;
        #pragma unroll
        for (int o = 16; o > 0; o >>= 1) p += __shfl_xor_sync(0xffffffffu, p, o);
        s[i] = p;
    }
    // exact top-8 of the 16 rescored candidates
    float bs[8]; int bp[8];
    #pragma unroll
    for (int j = 0; j < 8; j++) { bs[j] = -3.4e38f; bp[j] = 0; }
    #pragma unroll
    for (int i = 0; i < NCAND; i++) {
        if (s[i] > bs[7]) {
            bs[7] = s[i]; bp[7] = i;
            #pragma unroll
            for (int j = 7; j > 0; j--) {
                if (bs[j] > bs[j - 1]) {
                    float tf = bs[j]; bs[j] = bs[j - 1]; bs[j - 1] = tf;
                    int   tt = bp[j]; bp[j] = bp[j - 1]; bp[j - 1] = tt;
                }
            }
        }
    }
    const float mx = bs[0];
    float w[8]; float z = 0.f;
    #pragma unroll
    for (int i = 0; i < 8; i++) { w[i] = __expf(bs[i] - mx); z += w[i]; }
    const float rz = 1.f / z;

    float r[8];
    #pragma unroll
    for (int j = 0; j < 8; j++) r[j] = 0.f;
    #pragma unroll
    for (int i = 0; i < 8; i++) {
        const float wi = w[i] * rz;
        const float* vr = vals + (size_t)id[bp[i]] * FD + lane * 8;
        float4 v1 = *(const float4*)&vr[0];
        float4 v2 = *(const float4*)&vr[4];
        r[0] = fmaf(wi, v1.x, r[0]); r[1] = fmaf(wi, v1.y, r[1]);
        r[2] = fmaf(wi, v1.z, r[2]); r[3] = fmaf(wi, v1.w, r[3]);
        r[4] = fmaf(wi, v2.x, r[4]); r[5] = fmaf(wi, v2.y, r[5]);
        r[6] = fmaf(wi, v2.z, r[6]); r[7] = fmaf(wi, v2.w, r[7]);
    }
    __nv_bfloat16 hv[8], lv[8];
    #pragma unroll
    for (int j = 0; j < 8; j++) {
        hv[j] = __float2bfloat16(r[j]);
        lv[j] = __float2bfloat16(r[j] - __bfloat162float(hv[j]));
    }
    const size_t off = (size_t)gwarp * FD + lane * 8;
    *(uint4*)&g_rhi[off] = *(uint4*)hv;
    *(uint4*)&g_rlo[off] = *(uint4*)lv;
}

// ---------------- launch ----------------
extern "C" void kernel_launch(void* const* d_in, const int* in_sizes, int n_in,
                              void* d_out, int out_size) {
    const float* query = (const float*)d_in[0];
    const float* mkeys = (const float*)d_in[1];
    const float* mvals = (const float*)d_in[2];
    const float* Wq    = (const float*)d_in[3];
    const float* bq    = (const float*)d_in[4];
    const float* W1    = (const float*)d_in[5];
    const float* b1    = (const float*)d_in[6];
    const float* W2    = (const float*)d_in[7];
    const float* b2    = (const float*)d_in[8];
    float* out = (float*)d_out;

    cudaFuncSetAttribute(sim_topk_kernel, cudaFuncAttributeMaxDynamicSharedMemorySize, SIM_SMEM);
    cudaFuncSetAttribute(bgemm<0>, cudaFuncAttributeMaxDynamicSharedMemorySize, BG_SMEM);
    cudaFuncSetAttribute(bgemm<1>, cudaFuncAttributeMaxDynamicSharedMemorySize, BG_SMEM);
    cudaFuncSetAttribute(bgemm<2>, cudaFuncAttributeMaxDynamicSharedMemorySize, BG_SMEM);

    // launch order keeps sim_topk at index 3 (ncu capture slot)
    cvt_kw_kernel<<<(MSZ * FD / 2 + 4 * FD * FD + 255) / 256, 256>>>(mkeys, Wq, W1, W2); // 0
    cvt_query_split_kernel<<<(TOKENS * FD + 255) / 256, 256>>>(query);                   // 1
    bgemm<0><<<dim3(2, 512), 256, BG_SMEM>>>(bq, nullptr);                               // 2
    sim_topk_kernel<<<TOKENS / 64, 256, SIM_SMEM>>>();                                   // 3
    retrieve_kernel<<<(TOKENS * 32) / 256, 256>>>(mkeys, mvals);                         // 4
    bgemm<1><<<dim3(2, 512), 256, BG_SMEM>>>(b1, nullptr);                               // 5
    bgemm<2><<<dim3(2, 512), 256, BG_SMEM>>>(b2, out);                                   // 6
}